// round 1
// baseline (speedup 1.0000x reference)
#include <cuda_runtime.h>
#include <cstdint>
#include <cstddef>

#define Tseq 4096
#define CDIM 1024
#define NH   16
#define HD   64

// ---------------- scratch (device globals: no allocation allowed) ----------
__device__ float g_Q[Tseq * CDIM];
__device__ float g_K[Tseq * CDIM];
__device__ float g_V[Tseq * CDIM];
__device__ float g_O[Tseq * CDIM];

// ---------------- SGEMM: C[M,N] = A[M,K] @ B[N,K]^T  (all row-major) -------
// Fixed shape: M=4096, N=1024, K=1024. Tile 128x128x16, 256 threads, 8x8/thread.
constexpr int BM = 128, BN = 128, BK = 16;

__device__ __forceinline__ void sgemm_body(const float* __restrict__ A,
                                           const float* __restrict__ B,
                                           float* __restrict__ C)
{
    __shared__ float As[BK][BM + 4];
    __shared__ float Bs[BK][BN + 4];

    const int tid = threadIdx.x;
    const int bm = blockIdx.y * BM;
    const int bn = blockIdx.x * BN;
    const int tx = tid & 15;
    const int ty = tid >> 4;

    // global->reg load mapping: 512 float4 slots; thread handles slot tid and tid+256
    const int r0 = tid >> 2;
    const int c0 = (tid & 3) * 4;
    const int r1 = r0 + 64;

    const float* Ap0 = A + (size_t)(bm + r0) * CDIM + c0;
    const float* Ap1 = A + (size_t)(bm + r1) * CDIM + c0;
    const float* Bp0 = B + (size_t)(bn + r0) * CDIM + c0;
    const float* Bp1 = B + (size_t)(bn + r1) * CDIM + c0;

    float acc[8][8];
#pragma unroll
    for (int i = 0; i < 8; i++)
#pragma unroll
        for (int j = 0; j < 8; j++) acc[i][j] = 0.f;

    float4 pa0 = *(const float4*)(Ap0);
    float4 pa1 = *(const float4*)(Ap1);
    float4 pb0 = *(const float4*)(Bp0);
    float4 pb1 = *(const float4*)(Bp1);

    for (int k0 = 0; k0 < CDIM; k0 += BK) {
        // store current tile to smem (transposed: [k][m])
        As[c0 + 0][r0] = pa0.x; As[c0 + 1][r0] = pa0.y; As[c0 + 2][r0] = pa0.z; As[c0 + 3][r0] = pa0.w;
        As[c0 + 0][r1] = pa1.x; As[c0 + 1][r1] = pa1.y; As[c0 + 2][r1] = pa1.z; As[c0 + 3][r1] = pa1.w;
        Bs[c0 + 0][r0] = pb0.x; Bs[c0 + 1][r0] = pb0.y; Bs[c0 + 2][r0] = pb0.z; Bs[c0 + 3][r0] = pb0.w;
        Bs[c0 + 0][r1] = pb1.x; Bs[c0 + 1][r1] = pb1.y; Bs[c0 + 2][r1] = pb1.z; Bs[c0 + 3][r1] = pb1.w;
        __syncthreads();

        // prefetch next tile into registers
        if (k0 + BK < CDIM) {
            pa0 = *(const float4*)(Ap0 + k0 + BK);
            pa1 = *(const float4*)(Ap1 + k0 + BK);
            pb0 = *(const float4*)(Bp0 + k0 + BK);
            pb1 = *(const float4*)(Bp1 + k0 + BK);
        }

#pragma unroll
        for (int kk = 0; kk < BK; kk++) {
            float4 a0 = *(const float4*)&As[kk][ty * 8];
            float4 a1 = *(const float4*)&As[kk][ty * 8 + 4];
            float4 b0 = *(const float4*)&Bs[kk][tx * 8];
            float4 b1 = *(const float4*)&Bs[kk][tx * 8 + 4];
            float av[8] = {a0.x, a0.y, a0.z, a0.w, a1.x, a1.y, a1.z, a1.w};
            float bv[8] = {b0.x, b0.y, b0.z, b0.w, b1.x, b1.y, b1.z, b1.w};
#pragma unroll
            for (int i = 0; i < 8; i++)
#pragma unroll
                for (int j = 0; j < 8; j++)
                    acc[i][j] += av[i] * bv[j];
        }
        __syncthreads();
    }

#pragma unroll
    for (int i = 0; i < 8; i++) {
        float* Cp = C + (size_t)(bm + ty * 8 + i) * CDIM + bn + tx * 8;
        *(float4*)(Cp)     = make_float4(acc[i][0], acc[i][1], acc[i][2], acc[i][3]);
        *(float4*)(Cp + 4) = make_float4(acc[i][4], acc[i][5], acc[i][6], acc[i][7]);
    }
}

__global__ __launch_bounds__(256) void qkv_kernel(const float* __restrict__ x,
                                                  const float* __restrict__ Wq,
                                                  const float* __restrict__ Wk,
                                                  const float* __restrict__ Wv)
{
    const float* W = (blockIdx.z == 0) ? Wq : (blockIdx.z == 1) ? Wk : Wv;
    float* Cp = (blockIdx.z == 0) ? g_Q : (blockIdx.z == 1) ? g_K : g_V;
    sgemm_body(x, W, Cp);
}

__global__ __launch_bounds__(256) void oproj_kernel(const float* __restrict__ Wo,
                                                    float* __restrict__ out)
{
    sgemm_body(g_O, Wo, out);
}

// ---------------- sparse attention ----------------
// Mask: causal AND (delta<=255 OR delta%64==0). For key-block kb <= qb-5, only
// the diagonal (j == tid) survives -> single 64-dot per thread.
#define SMP 68   // padded smem row stride (float4-aligned, conflict-reducing)

__global__ __launch_bounds__(64) void attn_kernel()
{
    extern __shared__ float sm[];
    float* Ks = sm;
    float* Vs = sm + 64 * SMP;
    float* Ss = sm + 2 * 64 * SMP;

    const int qb = blockIdx.x;
    const int h  = blockIdx.y;
    const int tid = threadIdx.x;
    const int r = qb * 64 + tid;
    const float scale = 0.125f;  // 64^-0.5

    float q[HD];
    const float* Qp = g_Q + (size_t)r * CDIM + h * HD;
#pragma unroll
    for (int d = 0; d < HD; d += 4) {
        float4 t = *(const float4*)(Qp + d);
        q[d] = t.x; q[d + 1] = t.y; q[d + 2] = t.z; q[d + 3] = t.w;
    }

    float m = -1e30f, l = 0.f;
    float acc[HD];
#pragma unroll
    for (int d = 0; d < HD; d++) acc[d] = 0.f;

    for (int kb = 0; kb <= qb; ++kb) {
        const float* Kg = g_K + (size_t)(kb * 64) * CDIM + h * HD;
        const float* Vg = g_V + (size_t)(kb * 64) * CDIM + h * HD;

        __syncthreads();
        // cooperative coalesced tile load: 64 rows x 16 float4
#pragma unroll
        for (int v = 0; v < 16; v++) {
            int idx = v * 64 + tid;
            int row = idx >> 4;
            int cg = (idx & 15) * 4;
            *(float4*)&Ks[row * SMP + cg] = *(const float4*)(Kg + row * CDIM + cg);
            *(float4*)&Vs[row * SMP + cg] = *(const float4*)(Vg + row * CDIM + cg);
        }
        __syncthreads();

        if (kb >= qb - 4) {
            // window / mixed region: full masked 64-key block
            float bmax = -1e30f;
            for (int j = 0; j < 64; ++j) {
                const float* kr = &Ks[j * SMP];
                float s0 = 0.f, s1 = 0.f, s2 = 0.f, s3 = 0.f;
#pragma unroll
                for (int d4 = 0; d4 < 16; ++d4) {
                    float4 kv = *(const float4*)(kr + d4 * 4);
                    s0 += q[d4 * 4 + 0] * kv.x;
                    s1 += q[d4 * 4 + 1] * kv.y;
                    s2 += q[d4 * 4 + 2] * kv.z;
                    s3 += q[d4 * 4 + 3] * kv.w;
                }
                int delta = r - (kb * 64 + j);
                bool valid = (delta >= 0) && ((delta <= 255) || ((delta & 63) == 0));
                float s = valid ? (s0 + s1 + s2 + s3) * scale : -1e30f;
                Ss[tid * SMP + j] = s;
                bmax = fmaxf(bmax, s);
            }
            if (bmax > -1e29f) {
                float mnew = fmaxf(m, bmax);
                float corr = __expf(m - mnew);
                l *= corr;
#pragma unroll
                for (int d = 0; d < HD; d++) acc[d] *= corr;
                float lad = 0.f;
                for (int j = 0; j < 64; ++j) {
                    float p = __expf(Ss[tid * SMP + j] - mnew);
                    lad += p;
                    const float* vr = &Vs[j * SMP];
#pragma unroll
                    for (int d4 = 0; d4 < 16; d4++) {
                        float4 vv = *(const float4*)(vr + d4 * 4);
                        acc[d4 * 4 + 0] += p * vv.x;
                        acc[d4 * 4 + 1] += p * vv.y;
                        acc[d4 * 4 + 2] += p * vv.z;
                        acc[d4 * 4 + 3] += p * vv.w;
                    }
                }
                l += lad;
                m = mnew;
            }
        } else {
            // distant strided block: only the diagonal element j == tid
            const float* kr = &Ks[tid * SMP];
            float s0 = 0.f, s1 = 0.f, s2 = 0.f, s3 = 0.f;
#pragma unroll
            for (int d4 = 0; d4 < 16; ++d4) {
                float4 kv = *(const float4*)(kr + d4 * 4);
                s0 += q[d4 * 4 + 0] * kv.x;
                s1 += q[d4 * 4 + 1] * kv.y;
                s2 += q[d4 * 4 + 2] * kv.z;
                s3 += q[d4 * 4 + 3] * kv.w;
            }
            float s = (s0 + s1 + s2 + s3) * scale;
            float mnew = fmaxf(m, s);
            float corr = __expf(m - mnew);
            float p = __expf(s - mnew);
            l = l * corr + p;
            const float* vr = &Vs[tid * SMP];
#pragma unroll
            for (int d4 = 0; d4 < 16; d4++) {
                float4 vv = *(const float4*)(vr + d4 * 4);
                acc[d4 * 4 + 0] = acc[d4 * 4 + 0] * corr + p * vv.x;
                acc[d4 * 4 + 1] = acc[d4 * 4 + 1] * corr + p * vv.y;
                acc[d4 * 4 + 2] = acc[d4 * 4 + 2] * corr + p * vv.z;
                acc[d4 * 4 + 3] = acc[d4 * 4 + 3] * corr + p * vv.w;
            }
            m = mnew;
        }
    }

    // normalize + coalesced store via smem staging
    float inv = 1.0f / l;
    __syncthreads();
#pragma unroll
    for (int d = 0; d < HD; d++) Ss[tid * SMP + d] = acc[d] * inv;
    __syncthreads();
    float* Op = g_O + (size_t)(qb * 64) * CDIM + h * HD;
#pragma unroll
    for (int v = 0; v < 16; v++) {
        int idx = v * 64 + tid;
        int row = idx >> 4;
        int cg = (idx & 15) * 4;
        *(float4*)(Op + row * CDIM + cg) = *(const float4*)&Ss[row * SMP + cg];
    }
}

// ---------------- launch ----------------
extern "C" void kernel_launch(void* const* d_in, const int* in_sizes, int n_in,
                              void* d_out, int out_size)
{
    const float* x  = (const float*)d_in[0];
    const float* Wq = (const float*)d_in[1];
    const float* Wk = (const float*)d_in[2];
    const float* Wv = (const float*)d_in[3];
    const float* Wo = (const float*)d_in[4];
    float* out = (float*)d_out;

    // attention smem = 3 * 64 * 68 * 4 = 52224 B (> 48K default)
    cudaFuncSetAttribute(attn_kernel, cudaFuncAttributeMaxDynamicSharedMemorySize, 53248);

    dim3 gqkv(CDIM / BN, Tseq / BM, 3);
    qkv_kernel<<<gqkv, 256>>>(x, Wq, Wk, Wv);

    dim3 gattn(Tseq / 64, NH);
    attn_kernel<<<gattn, 64, 52224>>>();

    dim3 gout(CDIM / BN, Tseq / BM);
    oproj_kernel<<<gout, 256>>>(Wo, out);
}

// round 4
// speedup vs baseline: 1.4645x; 1.4645x over previous
#include <cuda_runtime.h>
#include <cuda_bf16.h>
#include <cstdint>
#include <cstddef>

using bf16 = __nv_bfloat16;

#define Tseq 4096
#define CDIM 1024
#define NH   16
#define HD   64
#define WSZ  (CDIM * CDIM)

// ---------------- scratch (device globals: no allocation allowed) ----------
__device__ float g_Q[Tseq * CDIM];
__device__ float g_K[Tseq * CDIM];
__device__ float g_V[Tseq * CDIM];
__device__ float g_O[Tseq * CDIM];
__device__ bf16  g_xh[Tseq * CDIM];
__device__ bf16  g_xl[Tseq * CDIM];
__device__ bf16  g_oh[Tseq * CDIM];
__device__ bf16  g_ol[Tseq * CDIM];
__device__ bf16  g_wh[4 * WSZ];
__device__ bf16  g_wl[4 * WSZ];

// ---------------- helpers ----------------
__device__ __forceinline__ uint32_t smem_u32(const void* p) {
    uint32_t a;
    asm("{ .reg .u64 t; cvta.to.shared.u64 t, %1; cvt.u32.u64 %0, t; }" : "=r"(a) : "l"(p));
    return a;
}

#define LDSM_X4(r0, r1, r2, r3, addr) \
    asm volatile("ldmatrix.sync.aligned.m8n8.x4.shared.b16 {%0,%1,%2,%3}, [%4];" \
                 : "=r"(r0), "=r"(r1), "=r"(r2), "=r"(r3) : "r"(addr))

#define MMA_BF16(c, a, b0, b1) \
    asm volatile("mma.sync.aligned.m16n8k16.row.col.f32.bf16.bf16.f32 " \
                 "{%0,%1,%2,%3}, {%4,%5,%6,%7}, {%8,%9}, {%0,%1,%2,%3};" \
                 : "+f"((c)[0]), "+f"((c)[1]), "+f"((c)[2]), "+f"((c)[3]) \
                 : "r"((a)[0]), "r"((a)[1]), "r"((a)[2]), "r"((a)[3]), "r"(b0), "r"(b1))

#define CP_ASYNC16(s, g) \
    asm volatile("cp.async.cg.shared.global [%0], [%1], 16;" :: "r"(s), "l"(g))
#define CP_COMMIT()  asm volatile("cp.async.commit_group;" ::: "memory")
#define CP_WAIT1()   asm volatile("cp.async.wait_group 1;" ::: "memory")
#define CP_WAIT0()   asm volatile("cp.async.wait_group 0;" ::: "memory")

// ---------------- fp32 -> bf16 hi/lo split ----------------
__global__ __launch_bounds__(256) void convert_split(const float* __restrict__ src,
                                                     bf16* __restrict__ dh,
                                                     bf16* __restrict__ dl, int n4)
{
    int i = blockIdx.x * blockDim.x + threadIdx.x;
    if (i >= n4) return;
    float4 v = ((const float4*)src)[i];
    bf16 h[4], l[4];
    float a[4] = {v.x, v.y, v.z, v.w};
#pragma unroll
    for (int k = 0; k < 4; k++) {
        h[k] = __float2bfloat16(a[k]);
        l[k] = __float2bfloat16(a[k] - __bfloat162float(h[k]));
    }
    *(uint2*)(dh + 4 * (size_t)i) = *(uint2*)h;
    *(uint2*)(dl + 4 * (size_t)i) = *(uint2*)l;
}

// ---------------- mma.sync bf16x3 GEMM: C[4096,1024] = A @ B^T -------------
// CTA tile 128x128, BK=64. 256 threads = 8 warps (4 M x 2 N), warp tile 32x64.
// smem: 2 buffers x 4 tiles (Ah, Al, Bh, Bl) x 16KB = 131072 bytes.
// Tile layout: 128 rows x 64 bf16 (128B rows), 16B slot swizzle: slot ^ (row & 7).
constexpr int TILE_B = 16384;
constexpr int BUF_B  = 4 * TILE_B;
constexpr int SMEM_GEMM = 2 * BUF_B;

__device__ __forceinline__ void load_tile_async(const bf16* __restrict__ g, int row0,
                                                int k0, uint32_t s_tile, int tid)
{
#pragma unroll
    for (int i = 0; i < 4; i++) {
        int id = tid + i * 256;
        int r = id >> 3;
        int slot = id & 7;
        const bf16* gp = g + (size_t)(row0 + r) * CDIM + k0 + slot * 8;
        uint32_t soff = r * 128 + ((slot ^ (r & 7)) * 16);
        CP_ASYNC16(s_tile + soff, gp);
    }
}

__device__ __forceinline__ void gemm_body(const bf16* __restrict__ Ah,
                                          const bf16* __restrict__ Al,
                                          const bf16* __restrict__ Bh,
                                          const bf16* __restrict__ Bl,
                                          float* __restrict__ C)
{
    extern __shared__ __align__(1024) unsigned char dynsmem[];
    uint32_t sb = smem_u32(dynsmem);
    const int tid = threadIdx.x;
    const int lane = tid & 31;
    const int wid = tid >> 5;
    const int bm = blockIdx.y * 128;
    const int bn = blockIdx.x * 128;
    const int m0 = (wid & 3) * 32;
    const int n0 = (wid >> 2) * 64;

    float acc[2][8][4];
#pragma unroll
    for (int mt = 0; mt < 2; mt++)
#pragma unroll
        for (int nt = 0; nt < 8; nt++)
#pragma unroll
            for (int c = 0; c < 4; c++) acc[mt][nt][c] = 0.f;

    // prologue: stage first two K-chunks
#pragma unroll
    for (int kt = 0; kt < 2; kt++) {
        uint32_t bufb = sb + kt * BUF_B;
        int k0 = kt * 64;
        load_tile_async(Ah, bm, k0, bufb + 0 * TILE_B, tid);
        load_tile_async(Al, bm, k0, bufb + 1 * TILE_B, tid);
        load_tile_async(Bh, bn, k0, bufb + 2 * TILE_B, tid);
        load_tile_async(Bl, bn, k0, bufb + 3 * TILE_B, tid);
        CP_COMMIT();
    }

    // fragment addressing constants
    const int arow_in = lane & 15;         // A: row within 16-row tile
    const int aslot_in = lane >> 4;        // A: +0/+1 slot
    const int bmat = lane >> 3;
    const int brow_in = ((bmat & 2) ? 8 : 0) + (lane & 7);
    const int bslot_in = bmat & 1;

#pragma unroll 1
    for (int kt = 0; kt < 16; ++kt) {
        if (kt < 15) CP_WAIT1(); else CP_WAIT0();
        __syncthreads();
        uint32_t cb = sb + (kt & 1) * BUF_B;

#pragma unroll
        for (int kk = 0; kk < 4; ++kk) {
            int s0 = kk * 2;
            uint32_t ah[2][4], al[2][4], bh[4][4], bl[4][4];
#pragma unroll
            for (int mt = 0; mt < 2; mt++) {
                int r = m0 + mt * 16 + arow_in;
                uint32_t off = r * 128 + (((s0 + aslot_in) ^ (r & 7)) * 16);
                LDSM_X4(ah[mt][0], ah[mt][1], ah[mt][2], ah[mt][3], cb + 0 * TILE_B + off);
                LDSM_X4(al[mt][0], al[mt][1], al[mt][2], al[mt][3], cb + 1 * TILE_B + off);
            }
#pragma unroll
            for (int np = 0; np < 4; np++) {
                int r = n0 + np * 16 + brow_in;
                uint32_t off = r * 128 + (((s0 + bslot_in) ^ (r & 7)) * 16);
                LDSM_X4(bh[np][0], bh[np][1], bh[np][2], bh[np][3], cb + 2 * TILE_B + off);
                LDSM_X4(bl[np][0], bl[np][1], bl[np][2], bl[np][3], cb + 3 * TILE_B + off);
            }
#pragma unroll
            for (int mt = 0; mt < 2; mt++)
#pragma unroll
                for (int np = 0; np < 4; np++) {
                    MMA_BF16(acc[mt][2 * np],     ah[mt], bh[np][0], bh[np][1]);
                    MMA_BF16(acc[mt][2 * np],     al[mt], bh[np][0], bh[np][1]);
                    MMA_BF16(acc[mt][2 * np],     ah[mt], bl[np][0], bl[np][1]);
                    MMA_BF16(acc[mt][2 * np + 1], ah[mt], bh[np][2], bh[np][3]);
                    MMA_BF16(acc[mt][2 * np + 1], al[mt], bh[np][2], bh[np][3]);
                    MMA_BF16(acc[mt][2 * np + 1], ah[mt], bl[np][2], bl[np][3]);
                }
        }
        __syncthreads();
        if (kt + 2 < 16) {
            uint32_t bufb = sb + (kt & 1) * BUF_B;
            int k0 = (kt + 2) * 64;
            load_tile_async(Ah, bm, k0, bufb + 0 * TILE_B, tid);
            load_tile_async(Al, bm, k0, bufb + 1 * TILE_B, tid);
            load_tile_async(Bh, bn, k0, bufb + 2 * TILE_B, tid);
            load_tile_async(Bl, bn, k0, bufb + 3 * TILE_B, tid);
            CP_COMMIT();
        }
    }

    // epilogue: direct global stores (disjoint per warp)
#pragma unroll
    for (int mt = 0; mt < 2; mt++) {
        int row = bm + m0 + mt * 16 + (lane >> 2);
#pragma unroll
        for (int nt = 0; nt < 8; nt++) {
            int col = bn + n0 + nt * 8 + 2 * (lane & 3);
            float* p = C + (size_t)row * CDIM + col;
            *(float2*)p = make_float2(acc[mt][nt][0], acc[mt][nt][1]);
            *(float2*)(p + 8 * CDIM) = make_float2(acc[mt][nt][2], acc[mt][nt][3]);
        }
    }
}

__global__ __launch_bounds__(256) void qkv_gemm()
{
    int z = blockIdx.z;
    const bf16* Bh = g_wh + (size_t)z * WSZ;
    const bf16* Bl = g_wl + (size_t)z * WSZ;
    float* C = (z == 0) ? g_Q : (z == 1) ? g_K : g_V;
    gemm_body(g_xh, g_xl, Bh, Bl, C);
}

__global__ __launch_bounds__(256) void oproj_gemm(float* __restrict__ out)
{
    gemm_body(g_oh, g_ol, g_wh + 3 * (size_t)WSZ, g_wl + 3 * (size_t)WSZ, out);
}

// ---------------- sparse attention ----------------
// Mask: causal AND (delta<=255 OR delta%64==0).
// Far blocks (kb <= qb-5): only diagonal j==tid -> per-thread direct L2 row loads.
// Window blocks (kb >= qb-4): full masked 64-key block via smem staging.
#define SMP 68

__global__ __launch_bounds__(64) void attn_kernel()
{
    extern __shared__ __align__(1024) unsigned char dynsmem[];
    float* sm = (float*)dynsmem;
    float* Ks = sm;
    float* Vs = sm + 64 * SMP;
    float* Ss = sm + 2 * 64 * SMP;

    const int qb = blockIdx.x;
    const int h  = blockIdx.y;
    const int tid = threadIdx.x;
    const int r = qb * 64 + tid;
    const float scale = 0.125f;

    float q[HD];
    const float* Qp = g_Q + (size_t)r * CDIM + h * HD;
#pragma unroll
    for (int d = 0; d < HD; d += 4) {
        float4 t = *(const float4*)(Qp + d);
        q[d] = t.x; q[d + 1] = t.y; q[d + 2] = t.z; q[d + 3] = t.w;
    }

    float m = -1e30f, l = 0.f;
    float acc[HD];
#pragma unroll
    for (int d = 0; d < HD; d++) acc[d] = 0.f;

    // ---- far strided blocks: direct per-thread row loads (no smem, no barriers)
#pragma unroll 2
    for (int kb = 0; kb + 5 <= qb; ++kb) {
        const float* kr = g_K + (size_t)(kb * 64 + tid) * CDIM + h * HD;
        float4 kreg[16];
#pragma unroll
        for (int d4 = 0; d4 < 16; ++d4) kreg[d4] = *(const float4*)(kr + d4 * 4);
        float s0 = 0.f, s1 = 0.f, s2 = 0.f, s3 = 0.f;
#pragma unroll
        for (int d4 = 0; d4 < 16; ++d4) {
            s0 += q[d4 * 4 + 0] * kreg[d4].x;
            s1 += q[d4 * 4 + 1] * kreg[d4].y;
            s2 += q[d4 * 4 + 2] * kreg[d4].z;
            s3 += q[d4 * 4 + 3] * kreg[d4].w;
        }
        float s = (s0 + s1 + s2 + s3) * scale;
        float mnew = fmaxf(m, s);
        float corr = __expf(m - mnew);
        float p = __expf(s - mnew);
        l = l * corr + p;
        const float* vr = g_V + (size_t)(kb * 64 + tid) * CDIM + h * HD;
#pragma unroll
        for (int d4 = 0; d4 < 16; d4++) {
            float4 vv = *(const float4*)(vr + d4 * 4);
            acc[d4 * 4 + 0] = acc[d4 * 4 + 0] * corr + p * vv.x;
            acc[d4 * 4 + 1] = acc[d4 * 4 + 1] * corr + p * vv.y;
            acc[d4 * 4 + 2] = acc[d4 * 4 + 2] * corr + p * vv.z;
            acc[d4 * 4 + 3] = acc[d4 * 4 + 3] * corr + p * vv.w;
        }
        m = mnew;
    }

    // ---- window blocks: staged, full masked compute
    int wstart = (qb >= 4) ? qb - 4 : 0;
    for (int kb = wstart; kb <= qb; ++kb) {
        const float* Kg = g_K + (size_t)(kb * 64) * CDIM + h * HD;
        const float* Vg = g_V + (size_t)(kb * 64) * CDIM + h * HD;

        __syncthreads();
#pragma unroll
        for (int v = 0; v < 16; v++) {
            int idx = v * 64 + tid;
            int row = idx >> 4;
            int cg = (idx & 15) * 4;
            *(float4*)&Ks[row * SMP + cg] = *(const float4*)(Kg + row * CDIM + cg);
            *(float4*)&Vs[row * SMP + cg] = *(const float4*)(Vg + row * CDIM + cg);
        }
        __syncthreads();

        float bmax = -1e30f;
        for (int j = 0; j < 64; ++j) {
            const float* kr = &Ks[j * SMP];
            float s0 = 0.f, s1 = 0.f, s2 = 0.f, s3 = 0.f;
#pragma unroll
            for (int d4 = 0; d4 < 16; ++d4) {
                float4 kv = *(const float4*)(kr + d4 * 4);
                s0 += q[d4 * 4 + 0] * kv.x;
                s1 += q[d4 * 4 + 1] * kv.y;
                s2 += q[d4 * 4 + 2] * kv.z;
                s3 += q[d4 * 4 + 3] * kv.w;
            }
            int delta = r - (kb * 64 + j);
            bool valid = (delta >= 0) && ((delta <= 255) || ((delta & 63) == 0));
            float s = valid ? (s0 + s1 + s2 + s3) * scale : -1e30f;
            Ss[tid * SMP + j] = s;
            bmax = fmaxf(bmax, s);
        }
        if (bmax > -1e29f) {
            float mnew = fmaxf(m, bmax);
            float corr = __expf(m - mnew);
            l *= corr;
#pragma unroll
            for (int d = 0; d < HD; d++) acc[d] *= corr;
            float lad = 0.f;
            for (int j = 0; j < 64; ++j) {
                float p = __expf(Ss[tid * SMP + j] - mnew);
                lad += p;
                const float* vr = &Vs[j * SMP];
#pragma unroll
                for (int d4 = 0; d4 < 16; d4++) {
                    float4 vv = *(const float4*)(vr + d4 * 4);
                    acc[d4 * 4 + 0] += p * vv.x;
                    acc[d4 * 4 + 1] += p * vv.y;
                    acc[d4 * 4 + 2] += p * vv.z;
                    acc[d4 * 4 + 3] += p * vv.w;
                }
            }
            l += lad;
            m = mnew;
        }
    }

    // normalize + coalesced store via smem staging
    float inv = 1.0f / l;
    __syncthreads();
#pragma unroll
    for (int d = 0; d < HD; d++) Ss[tid * SMP + d] = acc[d] * inv;
    __syncthreads();
    float* Op = g_O + (size_t)(qb * 64) * CDIM + h * HD;
#pragma unroll
    for (int v = 0; v < 16; v++) {
        int idx = v * 64 + tid;
        int row = idx >> 4;
        int cg = (idx & 15) * 4;
        *(float4*)(Op + row * CDIM + cg) = *(const float4*)&Ss[row * SMP + cg];
    }
}

// ---------------- launch ----------------
extern "C" void kernel_launch(void* const* d_in, const int* in_sizes, int n_in,
                              void* d_out, int out_size)
{
    const float* x  = (const float*)d_in[0];
    const float* Wq = (const float*)d_in[1];
    const float* Wk = (const float*)d_in[2];
    const float* Wv = (const float*)d_in[3];
    const float* Wo = (const float*)d_in[4];
    float* out = (float*)d_out;

    cudaFuncSetAttribute(attn_kernel, cudaFuncAttributeMaxDynamicSharedMemorySize, 53248);
    cudaFuncSetAttribute(qkv_gemm,   cudaFuncAttributeMaxDynamicSharedMemorySize, SMEM_GEMM);
    cudaFuncSetAttribute(oproj_gemm, cudaFuncAttributeMaxDynamicSharedMemorySize, SMEM_GEMM);

    bf16 *xh, *xl, *wh, *wl, *oh, *ol;
    cudaGetSymbolAddress((void**)&xh, g_xh);
    cudaGetSymbolAddress((void**)&xl, g_xl);
    cudaGetSymbolAddress((void**)&wh, g_wh);
    cudaGetSymbolAddress((void**)&wl, g_wl);
    cudaGetSymbolAddress((void**)&oh, g_oh);
    cudaGetSymbolAddress((void**)&ol, g_ol);
    float* oPtr;
    cudaGetSymbolAddress((void**)&oPtr, g_O);

    convert_split<<<(Tseq * CDIM / 4 + 255) / 256, 256>>>(x, xh, xl, Tseq * CDIM / 4);
    convert_split<<<(WSZ / 4 + 255) / 256, 256>>>(Wq, wh + 0 * (size_t)WSZ, wl + 0 * (size_t)WSZ, WSZ / 4);
    convert_split<<<(WSZ / 4 + 255) / 256, 256>>>(Wk, wh + 1 * (size_t)WSZ, wl + 1 * (size_t)WSZ, WSZ / 4);
    convert_split<<<(WSZ / 4 + 255) / 256, 256>>>(Wv, wh + 2 * (size_t)WSZ, wl + 2 * (size_t)WSZ, WSZ / 4);
    convert_split<<<(WSZ / 4 + 255) / 256, 256>>>(Wo, wh + 3 * (size_t)WSZ, wl + 3 * (size_t)WSZ, WSZ / 4);

    qkv_gemm<<<dim3(CDIM / 128, Tseq / 128, 3), 256, SMEM_GEMM>>>();

    attn_kernel<<<dim3(Tseq / 64, NH), 64, 52224>>>();

    convert_split<<<(Tseq * CDIM / 4 + 255) / 256, 256>>>(oPtr, oh, ol, Tseq * CDIM / 4);

    oproj_gemm<<<dim3(CDIM / 128, Tseq / 128), 256, SMEM_GEMM>>>(out);
}

// round 7
// speedup vs baseline: 2.2045x; 1.5053x over previous
#include <cuda_runtime.h>
#include <cuda_bf16.h>
#include <cstdint>
#include <cstddef>

using bf16 = __nv_bfloat16;

#define Tseq 4096
#define CDIM 1024
#define NH   16
#define HD   64
#define WSZ  (CDIM * CDIM)
#define NEG_INF (-1e30f)

// ---------------- scratch (device globals: no allocation allowed) ----------
__device__ float g_Q[Tseq * CDIM];
__device__ float g_K[Tseq * CDIM];
__device__ float g_V[Tseq * CDIM];
__device__ float g_O[Tseq * CDIM];
__device__ bf16  g_xh[Tseq * CDIM];
__device__ bf16  g_xl[Tseq * CDIM];
__device__ bf16  g_oh[Tseq * CDIM];
__device__ bf16  g_ol[Tseq * CDIM];
__device__ bf16  g_wh[4 * WSZ];
__device__ bf16  g_wl[4 * WSZ];

// ---------------- helpers ----------------
__device__ __forceinline__ uint32_t smem_u32(const void* p) {
    uint32_t a;
    asm("{ .reg .u64 t; cvta.to.shared.u64 t, %1; cvt.u32.u64 %0, t; }" : "=r"(a) : "l"(p));
    return a;
}

#define LDSM_X4(r0, r1, r2, r3, addr) \
    asm volatile("ldmatrix.sync.aligned.m8n8.x4.shared.b16 {%0,%1,%2,%3}, [%4];" \
                 : "=r"(r0), "=r"(r1), "=r"(r2), "=r"(r3) : "r"(addr))

#define LDSM_X4_T(r0, r1, r2, r3, addr) \
    asm volatile("ldmatrix.sync.aligned.m8n8.x4.trans.shared.b16 {%0,%1,%2,%3}, [%4];" \
                 : "=r"(r0), "=r"(r1), "=r"(r2), "=r"(r3) : "r"(addr))

#define MMA_BF16(c, a, b0, b1) \
    asm volatile("mma.sync.aligned.m16n8k16.row.col.f32.bf16.bf16.f32 " \
                 "{%0,%1,%2,%3}, {%4,%5,%6,%7}, {%8,%9}, {%0,%1,%2,%3};" \
                 : "+f"((c)[0]), "+f"((c)[1]), "+f"((c)[2]), "+f"((c)[3]) \
                 : "r"((a)[0]), "r"((a)[1]), "r"((a)[2]), "r"((a)[3]), "r"(b0), "r"(b1))

// d = {hi in high half, lo in low half}
#define PACK_BF16X2(d, hi, lo) \
    asm("cvt.rn.bf16x2.f32 %0, %1, %2;" : "=r"(d) : "f"(hi), "f"(lo))

#define CP_ASYNC16(s, g) \
    asm volatile("cp.async.cg.shared.global [%0], [%1], 16;" :: "r"(s), "l"(g))
#define CP_COMMIT()  asm volatile("cp.async.commit_group;" ::: "memory")
#define CP_WAIT1()   asm volatile("cp.async.wait_group 1;" ::: "memory")
#define CP_WAIT0()   asm volatile("cp.async.wait_group 0;" ::: "memory")

// split two floats into packed bf16 hi-parts (h2) and bf16 residual lo-parts (l2)
// low half of register = first arg (even col), high half = second arg (odd col)
__device__ __forceinline__ void split_pack2(float a, float b, uint32_t& h2, uint32_t& l2)
{
    PACK_BF16X2(h2, b, a);
    float ar = a - __bfloat162float(__float2bfloat16(a));
    float br = b - __bfloat162float(__float2bfloat16(b));
    PACK_BF16X2(l2, br, ar);
}

// ---------------- fp32 -> bf16 hi/lo split ----------------
__global__ __launch_bounds__(256) void convert_split(const float* __restrict__ src,
                                                     bf16* __restrict__ dh,
                                                     bf16* __restrict__ dl, int n4)
{
    int i = blockIdx.x * blockDim.x + threadIdx.x;
    if (i >= n4) return;
    float4 v = ((const float4*)src)[i];
    bf16 h[4], l[4];
    float a[4] = {v.x, v.y, v.z, v.w};
#pragma unroll
    for (int k = 0; k < 4; k++) {
        h[k] = __float2bfloat16(a[k]);
        l[k] = __float2bfloat16(a[k] - __bfloat162float(h[k]));
    }
    *(uint2*)(dh + 4 * (size_t)i) = *(uint2*)h;
    *(uint2*)(dl + 4 * (size_t)i) = *(uint2*)l;
}

// ---------------- mma.sync bf16x3 GEMM: C[4096,1024] = A @ B^T -------------
constexpr int TILE_B = 16384;
constexpr int BUF_B  = 4 * TILE_B;
constexpr int SMEM_GEMM = 2 * BUF_B;

__device__ __forceinline__ void load_tile_async(const bf16* __restrict__ g, int row0,
                                                int k0, uint32_t s_tile, int tid)
{
#pragma unroll
    for (int i = 0; i < 4; i++) {
        int id = tid + i * 256;
        int r = id >> 3;
        int slot = id & 7;
        const bf16* gp = g + (size_t)(row0 + r) * CDIM + k0 + slot * 8;
        uint32_t soff = r * 128 + ((slot ^ (r & 7)) * 16);
        CP_ASYNC16(s_tile + soff, gp);
    }
}

__device__ __forceinline__ void gemm_body(const bf16* __restrict__ Ah,
                                          const bf16* __restrict__ Al,
                                          const bf16* __restrict__ Bh,
                                          const bf16* __restrict__ Bl,
                                          float* __restrict__ C)
{
    extern __shared__ __align__(1024) unsigned char dynsmem[];
    uint32_t sb = smem_u32(dynsmem);
    const int tid = threadIdx.x;
    const int lane = tid & 31;
    const int wid = tid >> 5;
    const int bm = blockIdx.y * 128;
    const int bn = blockIdx.x * 128;
    const int m0 = (wid & 3) * 32;
    const int n0 = (wid >> 2) * 64;

    float acc[2][8][4];
#pragma unroll
    for (int mt = 0; mt < 2; mt++)
#pragma unroll
        for (int nt = 0; nt < 8; nt++)
#pragma unroll
            for (int c = 0; c < 4; c++) acc[mt][nt][c] = 0.f;

#pragma unroll
    for (int kt = 0; kt < 2; kt++) {
        uint32_t bufb = sb + kt * BUF_B;
        int k0 = kt * 64;
        load_tile_async(Ah, bm, k0, bufb + 0 * TILE_B, tid);
        load_tile_async(Al, bm, k0, bufb + 1 * TILE_B, tid);
        load_tile_async(Bh, bn, k0, bufb + 2 * TILE_B, tid);
        load_tile_async(Bl, bn, k0, bufb + 3 * TILE_B, tid);
        CP_COMMIT();
    }

    const int arow_in = lane & 15;
    const int aslot_in = lane >> 4;
    const int bmat = lane >> 3;
    const int brow_in = ((bmat & 2) ? 8 : 0) + (lane & 7);
    const int bslot_in = bmat & 1;

#pragma unroll 1
    for (int kt = 0; kt < 16; ++kt) {
        if (kt < 15) CP_WAIT1(); else CP_WAIT0();
        __syncthreads();
        uint32_t cb = sb + (kt & 1) * BUF_B;

#pragma unroll
        for (int kk = 0; kk < 4; ++kk) {
            int s0 = kk * 2;
            uint32_t ah[2][4], al[2][4], bh[4][4], bl[4][4];
#pragma unroll
            for (int mt = 0; mt < 2; mt++) {
                int r = m0 + mt * 16 + arow_in;
                uint32_t off = r * 128 + (((s0 + aslot_in) ^ (r & 7)) * 16);
                LDSM_X4(ah[mt][0], ah[mt][1], ah[mt][2], ah[mt][3], cb + 0 * TILE_B + off);
                LDSM_X4(al[mt][0], al[mt][1], al[mt][2], al[mt][3], cb + 1 * TILE_B + off);
            }
#pragma unroll
            for (int np = 0; np < 4; np++) {
                int r = n0 + np * 16 + brow_in;
                uint32_t off = r * 128 + (((s0 + bslot_in) ^ (r & 7)) * 16);
                LDSM_X4(bh[np][0], bh[np][1], bh[np][2], bh[np][3], cb + 2 * TILE_B + off);
                LDSM_X4(bl[np][0], bl[np][1], bl[np][2], bl[np][3], cb + 3 * TILE_B + off);
            }
#pragma unroll
            for (int mt = 0; mt < 2; mt++)
#pragma unroll
                for (int np = 0; np < 4; np++) {
                    MMA_BF16(acc[mt][2 * np],     ah[mt], bh[np][0], bh[np][1]);
                    MMA_BF16(acc[mt][2 * np],     al[mt], bh[np][0], bh[np][1]);
                    MMA_BF16(acc[mt][2 * np],     ah[mt], bl[np][0], bl[np][1]);
                    MMA_BF16(acc[mt][2 * np + 1], ah[mt], bh[np][2], bh[np][3]);
                    MMA_BF16(acc[mt][2 * np + 1], al[mt], bh[np][2], bh[np][3]);
                    MMA_BF16(acc[mt][2 * np + 1], ah[mt], bl[np][2], bl[np][3]);
                }
        }
        __syncthreads();
        if (kt + 2 < 16) {
            uint32_t bufb = sb + (kt & 1) * BUF_B;
            int k0 = (kt + 2) * 64;
            load_tile_async(Ah, bm, k0, bufb + 0 * TILE_B, tid);
            load_tile_async(Al, bm, k0, bufb + 1 * TILE_B, tid);
            load_tile_async(Bh, bn, k0, bufb + 2 * TILE_B, tid);
            load_tile_async(Bl, bn, k0, bufb + 3 * TILE_B, tid);
            CP_COMMIT();
        }
    }

#pragma unroll
    for (int mt = 0; mt < 2; mt++) {
        int row = bm + m0 + mt * 16 + (lane >> 2);
#pragma unroll
        for (int nt = 0; nt < 8; nt++) {
            int col = bn + n0 + nt * 8 + 2 * (lane & 3);
            float* p = C + (size_t)row * CDIM + col;
            *(float2*)p = make_float2(acc[mt][nt][0], acc[mt][nt][1]);
            *(float2*)(p + 8 * CDIM) = make_float2(acc[mt][nt][2], acc[mt][nt][3]);
        }
    }
}

__global__ __launch_bounds__(256) void qkv_gemm()
{
    int z = blockIdx.z;
    const bf16* Bh = g_wh + (size_t)z * WSZ;
    const bf16* Bl = g_wl + (size_t)z * WSZ;
    float* C = (z == 0) ? g_Q : (z == 1) ? g_K : g_V;
    gemm_body(g_xh, g_xl, Bh, Bl, C);
}

__global__ __launch_bounds__(256) void oproj_gemm(float* __restrict__ out)
{
    gemm_body(g_oh, g_ol, g_wh + 3 * (size_t)WSZ, g_wl + 3 * (size_t)WSZ, out);
}

// ---------------- hybrid sparse flash attention ----------------
// Block = (qb, h): 64 query rows, 128 threads = 4 warps x 16 rows.
// Far strided blocks (kb <= qb-5): exact scalar fp32, per-thread column
//   ownership matching the MMA accumulator layout; quad-shfl for the dot.
// Window blocks (kb >= qb-4): bf16 mma. Scores 3-pass hi/lo, PV 3-pass hi/lo.
// A-fragment reg order (PTX m16n8k16): (r,c), (r+8,c), (r,c+8), (r+8,c+8).

__device__ __forceinline__ void stage_hl(const float* __restrict__ g, int row0, int h,
                                         bf16* sh, bf16* sl, int tid)
{
#pragma unroll
    for (int s = 0; s < 4; s++) {
        int sid = tid + s * 128;
        int r = sid >> 3, sl8 = sid & 7;
        const float* src = g + (size_t)(row0 + r) * CDIM + h * HD + sl8 * 8;
        float4 v0 = *(const float4*)src;
        float4 v1 = *(const float4*)(src + 4);
        float a[8] = {v0.x, v0.y, v0.z, v0.w, v1.x, v1.y, v1.z, v1.w};
        bf16 hi[8], lo[8];
#pragma unroll
        for (int k = 0; k < 8; k++) {
            hi[k] = __float2bfloat16(a[k]);
            lo[k] = __float2bfloat16(a[k] - __bfloat162float(hi[k]));
        }
        uint32_t off = r * 128 + ((sl8 ^ (r & 7)) * 16);
        *(uint4*)((char*)sh + off) = *(uint4*)hi;
        *(uint4*)((char*)sl + off) = *(uint4*)lo;
    }
}

__global__ __launch_bounds__(128) void attn_kernel()
{
    __shared__ __align__(128) bf16 sKH[4096];
    __shared__ __align__(128) bf16 sKL[4096];
    __shared__ __align__(128) bf16 sVH[4096];
    __shared__ __align__(128) bf16 sVL[4096];

    const int qb = blockIdx.x;
    const int h  = blockIdx.y;
    const int tid = threadIdx.x;
    const int lane = tid & 31;
    const int w = tid >> 5;
    const int row16 = lane >> 2;
    const int quad = lane & 3;
    const int r0g = qb * 64 + w * 16 + row16;     // first owned query row
    const int rr0 = w * 16 + row16;               // row within 64-block

    // ---- scalar Q load (pre-scaled), dims {8j + 2*quad + {0,1}} ----
    float q0[16], q1[16];    // q0 = row r0g, q1 = row r0g+8
    {
        const float* qp0 = g_Q + (size_t)r0g * CDIM + h * HD;
#pragma unroll
        for (int j = 0; j < 8; j++) {
            float2 a = *(const float2*)(qp0 + 8 * j + 2 * quad);
            float2 b = *(const float2*)(qp0 + 8 * CDIM + 8 * j + 2 * quad);
            q0[2 * j] = a.x * 0.125f; q0[2 * j + 1] = a.y * 0.125f;
            q1[2 * j] = b.x * 0.125f; q1[2 * j + 1] = b.y * 0.125f;
        }
    }

    // ---- build Q mma fragments (hi/lo) from scalars ----
    // reg0 = (r,   16kk+2q+{0,1})   = q0[4kk+{0,1}]
    // reg1 = (r+8, 16kk+2q+{0,1})   = q1[4kk+{0,1}]
    // reg2 = (r,   16kk+8+2q+{0,1}) = q0[4kk+2+{0,1}]
    // reg3 = (r+8, 16kk+8+2q+{0,1}) = q1[4kk+2+{0,1}]
    uint32_t qh[4][4], ql[4][4];
#pragma unroll
    for (int kk = 0; kk < 4; kk++) {
        split_pack2(q0[4 * kk],     q0[4 * kk + 1], qh[kk][0], ql[kk][0]);
        split_pack2(q1[4 * kk],     q1[4 * kk + 1], qh[kk][1], ql[kk][1]);
        split_pack2(q0[4 * kk + 2], q0[4 * kk + 3], qh[kk][2], ql[kk][2]);
        split_pack2(q1[4 * kk + 2], q1[4 * kk + 3], qh[kk][3], ql[kk][3]);
    }

    float oacc[8][4];
#pragma unroll
    for (int t = 0; t < 8; t++)
#pragma unroll
        for (int c = 0; c < 4; c++) oacc[t][c] = 0.f;
    float m0 = NEG_INF, m1 = NEG_INF, l0 = 0.f, l1 = 0.f;

    // ================= far strided blocks: exact scalar =================
#pragma unroll 1
    for (int kb = 0; kb + 5 <= qb; ++kb) {
        const float* kp0 = g_K + (size_t)(kb * 64 + rr0) * CDIM + h * HD;
        const float* vp0 = g_V + (size_t)(kb * 64 + rr0) * CDIM + h * HD;
        float s0 = 0.f, s1 = 0.f;
#pragma unroll
        for (int j = 0; j < 8; j++) {
            float2 ka = *(const float2*)(kp0 + 8 * j + 2 * quad);
            float2 kb2 = *(const float2*)(kp0 + 8 * CDIM + 8 * j + 2 * quad);
            s0 += q0[2 * j] * ka.x + q0[2 * j + 1] * ka.y;
            s1 += q1[2 * j] * kb2.x + q1[2 * j + 1] * kb2.y;
        }
        s0 += __shfl_xor_sync(0xFFFFFFFFu, s0, 1);
        s0 += __shfl_xor_sync(0xFFFFFFFFu, s0, 2);
        s1 += __shfl_xor_sync(0xFFFFFFFFu, s1, 1);
        s1 += __shfl_xor_sync(0xFFFFFFFFu, s1, 2);
        float mn0 = fmaxf(m0, s0), mn1 = fmaxf(m1, s1);
        float c0 = __expf(m0 - mn0), c1 = __expf(m1 - mn1);
        float p0 = __expf(s0 - mn0), p1 = __expf(s1 - mn1);
        l0 = l0 * c0 + p0;
        l1 = l1 * c1 + p1;
#pragma unroll
        for (int j = 0; j < 8; j++) {
            float2 va = *(const float2*)(vp0 + 8 * j + 2 * quad);
            float2 vb2 = *(const float2*)(vp0 + 8 * CDIM + 8 * j + 2 * quad);
            oacc[j][0] = oacc[j][0] * c0 + p0 * va.x;
            oacc[j][1] = oacc[j][1] * c0 + p0 * va.y;
            oacc[j][2] = oacc[j][2] * c1 + p1 * vb2.x;
            oacc[j][3] = oacc[j][3] * c1 + p1 * vb2.y;
        }
        m0 = mn0; m1 = mn1;
    }

    // ================= window blocks: bf16 mma =================
    const uint32_t uKH = smem_u32(sKH), uKL = smem_u32(sKL);
    const uint32_t uVH = smem_u32(sVH), uVL = smem_u32(sVL);
    const int bmat = lane >> 3;
    const int brow_in = ((bmat & 2) ? 8 : 0) + (lane & 7);
    const int bslot_in = bmat & 1;
    const int v_row_in = ((lane >> 3) & 1) * 8 + (lane & 7);
    const int v_sel = lane >> 4;
    const int wstart = (qb >= 4) ? qb - 4 : 0;

#pragma unroll 1
    for (int kb = wstart; kb <= qb; ++kb) {
        __syncthreads();
        stage_hl(g_K, kb * 64, h, sKH, sKL, tid);
        stage_hl(g_V, kb * 64, h, sVH, sVL, tid);
        __syncthreads();

        // ---- scores: 3-pass hi/lo ----
        float sacc[8][4];
#pragma unroll
        for (int t = 0; t < 8; t++)
#pragma unroll
            for (int c = 0; c < 4; c++) sacc[t][c] = 0.f;
#pragma unroll
        for (int kk = 0; kk < 4; kk++) {
#pragma unroll
            for (int np = 0; np < 4; np++) {
                int r = np * 16 + brow_in;
                uint32_t off = r * 128 + (((2 * kk + bslot_in) ^ (r & 7)) * 16);
                uint32_t b[4];
                LDSM_X4(b[0], b[1], b[2], b[3], uKH + off);
                MMA_BF16(sacc[2 * np],     qh[kk], b[0], b[1]);
                MMA_BF16(sacc[2 * np + 1], qh[kk], b[2], b[3]);
                MMA_BF16(sacc[2 * np],     ql[kk], b[0], b[1]);
                MMA_BF16(sacc[2 * np + 1], ql[kk], b[2], b[3]);
                LDSM_X4(b[0], b[1], b[2], b[3], uKL + off);
                MMA_BF16(sacc[2 * np],     qh[kk], b[0], b[1]);
                MMA_BF16(sacc[2 * np + 1], qh[kk], b[2], b[3]);
            }
        }
        // ---- mask + online softmax ----
        float rmax0 = NEG_INF, rmax1 = NEG_INF;
#pragma unroll
        for (int t = 0; t < 8; t++) {
#pragma unroll
            for (int c = 0; c < 4; c++) {
                int row = r0g + ((c >> 1) ? 8 : 0);
                int col = kb * 64 + t * 8 + 2 * quad + (c & 1);
                int delta = row - col;
                bool valid = (delta >= 0) && ((delta <= 255) || ((delta & 63) == 0));
                float s = valid ? sacc[t][c] : NEG_INF;
                sacc[t][c] = s;
                if (c < 2) rmax0 = fmaxf(rmax0, s);
                else       rmax1 = fmaxf(rmax1, s);
            }
        }
        rmax0 = fmaxf(rmax0, __shfl_xor_sync(0xFFFFFFFFu, rmax0, 1));
        rmax0 = fmaxf(rmax0, __shfl_xor_sync(0xFFFFFFFFu, rmax0, 2));
        rmax1 = fmaxf(rmax1, __shfl_xor_sync(0xFFFFFFFFu, rmax1, 1));
        rmax1 = fmaxf(rmax1, __shfl_xor_sync(0xFFFFFFFFu, rmax1, 2));
        float mn0 = fmaxf(m0, rmax0), mn1 = fmaxf(m1, rmax1);
        float c0 = __expf(m0 - mn0), c1 = __expf(m1 - mn1);
        float sum0 = 0.f, sum1 = 0.f;
#pragma unroll
        for (int t = 0; t < 8; t++) {
#pragma unroll
            for (int c = 0; c < 4; c++) {
                float p = __expf(sacc[t][c] - ((c < 2) ? mn0 : mn1));
                sacc[t][c] = p;
                if (c < 2) sum0 += p; else sum1 += p;
            }
        }
        sum0 += __shfl_xor_sync(0xFFFFFFFFu, sum0, 1);
        sum0 += __shfl_xor_sync(0xFFFFFFFFu, sum0, 2);
        sum1 += __shfl_xor_sync(0xFFFFFFFFu, sum1, 1);
        sum1 += __shfl_xor_sync(0xFFFFFFFFu, sum1, 2);
        l0 = l0 * c0 + sum0;
        l1 = l1 * c1 + sum1;
#pragma unroll
        for (int t = 0; t < 8; t++) {
            oacc[t][0] *= c0; oacc[t][1] *= c0;
            oacc[t][2] *= c1; oacc[t][3] *= c1;
        }
        m0 = mn0; m1 = mn1;

        // ---- PV: 3-pass hi/lo ----
        // P a-frag regs: (r, j16+2q), (r+8, j16+2q), (r, j16+8+2q), (r+8, j16+8+2q)
#pragma unroll
        for (int j = 0; j < 4; j++) {
            uint32_t pfh[4], pfl[4];
            split_pack2(sacc[2 * j][0],     sacc[2 * j][1],     pfh[0], pfl[0]);
            split_pack2(sacc[2 * j][2],     sacc[2 * j][3],     pfh[1], pfl[1]);
            split_pack2(sacc[2 * j + 1][0], sacc[2 * j + 1][1], pfh[2], pfl[2]);
            split_pack2(sacc[2 * j + 1][2], sacc[2 * j + 1][3], pfh[3], pfl[3]);
#pragma unroll
            for (int np = 0; np < 4; np++) {
                int r = j * 16 + v_row_in;
                uint32_t off = r * 128 + (((2 * np + v_sel) ^ (r & 7)) * 16);
                uint32_t vh[4], vl[4];
                LDSM_X4_T(vh[0], vh[1], vh[2], vh[3], uVH + off);
                LDSM_X4_T(vl[0], vl[1], vl[2], vl[3], uVL + off);
                MMA_BF16(oacc[2 * np],     pfh, vh[0], vh[1]);
                MMA_BF16(oacc[2 * np],     pfl, vh[0], vh[1]);
                MMA_BF16(oacc[2 * np],     pfh, vl[0], vl[1]);
                MMA_BF16(oacc[2 * np + 1], pfh, vh[2], vh[3]);
                MMA_BF16(oacc[2 * np + 1], pfl, vh[2], vh[3]);
                MMA_BF16(oacc[2 * np + 1], pfh, vl[2], vl[3]);
            }
        }
    }

    // ---- normalize + store ----
    float inv0 = 1.f / l0, inv1 = 1.f / l1;
#pragma unroll
    for (int t = 0; t < 8; t++) {
        int col = h * HD + t * 8 + 2 * quad;
        float* p0 = g_O + (size_t)r0g * CDIM + col;
        float* p1 = g_O + (size_t)(r0g + 8) * CDIM + col;
        *(float2*)p0 = make_float2(oacc[t][0] * inv0, oacc[t][1] * inv0);
        *(float2*)p1 = make_float2(oacc[t][2] * inv1, oacc[t][3] * inv1);
    }
}

// ---------------- launch ----------------
extern "C" void kernel_launch(void* const* d_in, const int* in_sizes, int n_in,
                              void* d_out, int out_size)
{
    const float* x  = (const float*)d_in[0];
    const float* Wq = (const float*)d_in[1];
    const float* Wk = (const float*)d_in[2];
    const float* Wv = (const float*)d_in[3];
    const float* Wo = (const float*)d_in[4];
    float* out = (float*)d_out;

    cudaFuncSetAttribute(qkv_gemm,   cudaFuncAttributeMaxDynamicSharedMemorySize, SMEM_GEMM);
    cudaFuncSetAttribute(oproj_gemm, cudaFuncAttributeMaxDynamicSharedMemorySize, SMEM_GEMM);

    bf16 *xh, *xl, *wh, *wl, *oh, *ol;
    cudaGetSymbolAddress((void**)&xh, g_xh);
    cudaGetSymbolAddress((void**)&xl, g_xl);
    cudaGetSymbolAddress((void**)&wh, g_wh);
    cudaGetSymbolAddress((void**)&wl, g_wl);
    cudaGetSymbolAddress((void**)&oh, g_oh);
    cudaGetSymbolAddress((void**)&ol, g_ol);
    float* oPtr;
    cudaGetSymbolAddress((void**)&oPtr, g_O);

    convert_split<<<(Tseq * CDIM / 4 + 255) / 256, 256>>>(x, xh, xl, Tseq * CDIM / 4);
    convert_split<<<(WSZ / 4 + 255) / 256, 256>>>(Wq, wh + 0 * (size_t)WSZ, wl + 0 * (size_t)WSZ, WSZ / 4);
    convert_split<<<(WSZ / 4 + 255) / 256, 256>>>(Wk, wh + 1 * (size_t)WSZ, wl + 1 * (size_t)WSZ, WSZ / 4);
    convert_split<<<(WSZ / 4 + 255) / 256, 256>>>(Wv, wh + 2 * (size_t)WSZ, wl + 2 * (size_t)WSZ, WSZ / 4);
    convert_split<<<(WSZ / 4 + 255) / 256, 256>>>(Wo, wh + 3 * (size_t)WSZ, wl + 3 * (size_t)WSZ, WSZ / 4);

    qkv_gemm<<<dim3(CDIM / 128, Tseq / 128, 3), 256, SMEM_GEMM>>>();

    attn_kernel<<<dim3(Tseq / 64, NH), 128>>>();

    convert_split<<<(Tseq * CDIM / 4 + 255) / 256, 256>>>(oPtr, oh, ol, Tseq * CDIM / 4);

    oproj_gemm<<<dim3(CDIM / 128, Tseq / 128), 256, SMEM_GEMM>>>(out);
}

// round 8
// speedup vs baseline: 3.0799x; 1.3971x over previous
#include <cuda_runtime.h>
#include <cuda_bf16.h>
#include <cstdint>
#include <cstddef>

using bf16 = __nv_bfloat16;

#define Tseq 4096
#define CDIM 1024
#define NH   16
#define HD   64
#define WSZ  (CDIM * CDIM)
#define NEG_INF (-1e30f)

// ---------------- scratch (device globals: no allocation allowed) ----------
__device__ float g_Q[Tseq * CDIM];
__device__ float g_K[Tseq * CDIM];
__device__ float g_V[Tseq * CDIM];
__device__ float g_O[Tseq * CDIM];
__device__ float g_FO[Tseq * CDIM];     // far partial accumulators (un-normalized)
__device__ float g_fm[Tseq * NH];       // far partial row max
__device__ float g_fl[Tseq * NH];       // far partial row sum
__device__ bf16  g_xh[Tseq * CDIM];
__device__ bf16  g_xl[Tseq * CDIM];
__device__ bf16  g_oh[Tseq * CDIM];
__device__ bf16  g_ol[Tseq * CDIM];
__device__ bf16  g_wh[4 * WSZ];
__device__ bf16  g_wl[4 * WSZ];

// ---------------- helpers ----------------
__device__ __forceinline__ uint32_t smem_u32(const void* p) {
    uint32_t a;
    asm("{ .reg .u64 t; cvta.to.shared.u64 t, %1; cvt.u32.u64 %0, t; }" : "=r"(a) : "l"(p));
    return a;
}

#define LDSM_X4(r0, r1, r2, r3, addr) \
    asm volatile("ldmatrix.sync.aligned.m8n8.x4.shared.b16 {%0,%1,%2,%3}, [%4];" \
                 : "=r"(r0), "=r"(r1), "=r"(r2), "=r"(r3) : "r"(addr))

#define LDSM_X4_T(r0, r1, r2, r3, addr) \
    asm volatile("ldmatrix.sync.aligned.m8n8.x4.trans.shared.b16 {%0,%1,%2,%3}, [%4];" \
                 : "=r"(r0), "=r"(r1), "=r"(r2), "=r"(r3) : "r"(addr))

#define MMA_BF16(c, a, b0, b1) \
    asm volatile("mma.sync.aligned.m16n8k16.row.col.f32.bf16.bf16.f32 " \
                 "{%0,%1,%2,%3}, {%4,%5,%6,%7}, {%8,%9}, {%0,%1,%2,%3};" \
                 : "+f"((c)[0]), "+f"((c)[1]), "+f"((c)[2]), "+f"((c)[3]) \
                 : "r"((a)[0]), "r"((a)[1]), "r"((a)[2]), "r"((a)[3]), "r"(b0), "r"(b1))

// d = {hi arg in high half, lo arg in low half}
#define PACK_BF16X2(d, hi, lo) \
    asm("cvt.rn.bf16x2.f32 %0, %1, %2;" : "=r"(d) : "f"(hi), "f"(lo))

#define CP_ASYNC16(s, g) \
    asm volatile("cp.async.cg.shared.global [%0], [%1], 16;" :: "r"(s), "l"(g))
#define CP_COMMIT()  asm volatile("cp.async.commit_group;" ::: "memory")
#define CP_WAIT1()   asm volatile("cp.async.wait_group 1;" ::: "memory")
#define CP_WAIT0()   asm volatile("cp.async.wait_group 0;" ::: "memory")

// split two floats into packed bf16 hi-parts (h2) and bf16 residual lo-parts (l2)
__device__ __forceinline__ void split_pack2(float a, float b, uint32_t& h2, uint32_t& l2)
{
    PACK_BF16X2(h2, b, a);
    float ar = a - __bfloat162float(__float2bfloat16(a));
    float br = b - __bfloat162float(__float2bfloat16(b));
    PACK_BF16X2(l2, br, ar);
}

// ---------------- fp32 -> bf16 hi/lo split ----------------
__global__ __launch_bounds__(256) void convert_split(const float* __restrict__ src,
                                                     bf16* __restrict__ dh,
                                                     bf16* __restrict__ dl, int n4)
{
    int i = blockIdx.x * blockDim.x + threadIdx.x;
    if (i >= n4) return;
    float4 v = ((const float4*)src)[i];
    bf16 h[4], l[4];
    float a[4] = {v.x, v.y, v.z, v.w};
#pragma unroll
    for (int k = 0; k < 4; k++) {
        h[k] = __float2bfloat16(a[k]);
        l[k] = __float2bfloat16(a[k] - __bfloat162float(h[k]));
    }
    *(uint2*)(dh + 4 * (size_t)i) = *(uint2*)h;
    *(uint2*)(dl + 4 * (size_t)i) = *(uint2*)l;
}

// ---------------- mma.sync bf16x3 GEMM: C[4096,1024] = A @ B^T -------------
constexpr int TILE_B = 16384;
constexpr int BUF_B  = 4 * TILE_B;
constexpr int SMEM_GEMM = 2 * BUF_B;

__device__ __forceinline__ void load_tile_async(const bf16* __restrict__ g, int row0,
                                                int k0, uint32_t s_tile, int tid)
{
#pragma unroll
    for (int i = 0; i < 4; i++) {
        int id = tid + i * 256;
        int r = id >> 3;
        int slot = id & 7;
        const bf16* gp = g + (size_t)(row0 + r) * CDIM + k0 + slot * 8;
        uint32_t soff = r * 128 + ((slot ^ (r & 7)) * 16);
        CP_ASYNC16(s_tile + soff, gp);
    }
}

__device__ __forceinline__ void gemm_body(const bf16* __restrict__ Ah,
                                          const bf16* __restrict__ Al,
                                          const bf16* __restrict__ Bh,
                                          const bf16* __restrict__ Bl,
                                          float* __restrict__ C)
{
    extern __shared__ __align__(1024) unsigned char dynsmem[];
    uint32_t sb = smem_u32(dynsmem);
    const int tid = threadIdx.x;
    const int lane = tid & 31;
    const int wid = tid >> 5;
    const int bm = blockIdx.y * 128;
    const int bn = blockIdx.x * 128;
    const int m0 = (wid & 3) * 32;
    const int n0 = (wid >> 2) * 64;

    float acc[2][8][4];
#pragma unroll
    for (int mt = 0; mt < 2; mt++)
#pragma unroll
        for (int nt = 0; nt < 8; nt++)
#pragma unroll
            for (int c = 0; c < 4; c++) acc[mt][nt][c] = 0.f;

#pragma unroll
    for (int kt = 0; kt < 2; kt++) {
        uint32_t bufb = sb + kt * BUF_B;
        int k0 = kt * 64;
        load_tile_async(Ah, bm, k0, bufb + 0 * TILE_B, tid);
        load_tile_async(Al, bm, k0, bufb + 1 * TILE_B, tid);
        load_tile_async(Bh, bn, k0, bufb + 2 * TILE_B, tid);
        load_tile_async(Bl, bn, k0, bufb + 3 * TILE_B, tid);
        CP_COMMIT();
    }

    const int arow_in = lane & 15;
    const int aslot_in = lane >> 4;
    const int bmat = lane >> 3;
    const int brow_in = ((bmat & 2) ? 8 : 0) + (lane & 7);
    const int bslot_in = bmat & 1;

#pragma unroll 1
    for (int kt = 0; kt < 16; ++kt) {
        if (kt < 15) CP_WAIT1(); else CP_WAIT0();
        __syncthreads();
        uint32_t cb = sb + (kt & 1) * BUF_B;

#pragma unroll
        for (int kk = 0; kk < 4; ++kk) {
            int s0 = kk * 2;
            uint32_t ah[2][4], al[2][4], bh[4][4], bl[4][4];
#pragma unroll
            for (int mt = 0; mt < 2; mt++) {
                int r = m0 + mt * 16 + arow_in;
                uint32_t off = r * 128 + (((s0 + aslot_in) ^ (r & 7)) * 16);
                LDSM_X4(ah[mt][0], ah[mt][1], ah[mt][2], ah[mt][3], cb + 0 * TILE_B + off);
                LDSM_X4(al[mt][0], al[mt][1], al[mt][2], al[mt][3], cb + 1 * TILE_B + off);
            }
#pragma unroll
            for (int np = 0; np < 4; np++) {
                int r = n0 + np * 16 + brow_in;
                uint32_t off = r * 128 + (((s0 + bslot_in) ^ (r & 7)) * 16);
                LDSM_X4(bh[np][0], bh[np][1], bh[np][2], bh[np][3], cb + 2 * TILE_B + off);
                LDSM_X4(bl[np][0], bl[np][1], bl[np][2], bl[np][3], cb + 3 * TILE_B + off);
            }
#pragma unroll
            for (int mt = 0; mt < 2; mt++)
#pragma unroll
                for (int np = 0; np < 4; np++) {
                    MMA_BF16(acc[mt][2 * np],     ah[mt], bh[np][0], bh[np][1]);
                    MMA_BF16(acc[mt][2 * np],     al[mt], bh[np][0], bh[np][1]);
                    MMA_BF16(acc[mt][2 * np],     ah[mt], bl[np][0], bl[np][1]);
                    MMA_BF16(acc[mt][2 * np + 1], ah[mt], bh[np][2], bh[np][3]);
                    MMA_BF16(acc[mt][2 * np + 1], al[mt], bh[np][2], bh[np][3]);
                    MMA_BF16(acc[mt][2 * np + 1], ah[mt], bl[np][2], bl[np][3]);
                }
        }
        __syncthreads();
        if (kt + 2 < 16) {
            uint32_t bufb = sb + (kt & 1) * BUF_B;
            int k0 = (kt + 2) * 64;
            load_tile_async(Ah, bm, k0, bufb + 0 * TILE_B, tid);
            load_tile_async(Al, bm, k0, bufb + 1 * TILE_B, tid);
            load_tile_async(Bh, bn, k0, bufb + 2 * TILE_B, tid);
            load_tile_async(Bl, bn, k0, bufb + 3 * TILE_B, tid);
            CP_COMMIT();
        }
    }

#pragma unroll
    for (int mt = 0; mt < 2; mt++) {
        int row = bm + m0 + mt * 16 + (lane >> 2);
#pragma unroll
        for (int nt = 0; nt < 8; nt++) {
            int col = bn + n0 + nt * 8 + 2 * (lane & 3);
            float* p = C + (size_t)row * CDIM + col;
            *(float2*)p = make_float2(acc[mt][nt][0], acc[mt][nt][1]);
            *(float2*)(p + 8 * CDIM) = make_float2(acc[mt][nt][2], acc[mt][nt][3]);
        }
    }
}

__global__ __launch_bounds__(256) void qkv_gemm()
{
    int z = blockIdx.z;
    const bf16* Bh = g_wh + (size_t)z * WSZ;
    const bf16* Bl = g_wl + (size_t)z * WSZ;
    float* C = (z == 0) ? g_Q : (z == 1) ? g_K : g_V;
    gemm_body(g_xh, g_xl, Bh, Bl, C);
}

__global__ __launch_bounds__(256) void oproj_gemm(float* __restrict__ out)
{
    gemm_body(g_oh, g_ol, g_wh + 3 * (size_t)WSZ, g_wl + 3 * (size_t)WSZ, out);
}

// ---------------- attention helpers ----------------
// Stage 64 rows (row index = base + r*stride in g) x 64 dims of head h into
// hi/lo bf16 smem tiles (128B rows, slot^(r&7) swizzle).
__device__ __forceinline__ void stage_hl_s(const float* __restrict__ g, int base,
                                           int stride, int h, bf16* sh, bf16* sl,
                                           int tid)
{
#pragma unroll
    for (int s = 0; s < 4; s++) {
        int sid = tid + s * 128;
        int r = sid >> 3, sl8 = sid & 7;
        const float* src = g + (size_t)(base + r * stride) * CDIM + h * HD + sl8 * 8;
        float4 v0 = *(const float4*)src;
        float4 v1 = *(const float4*)(src + 4);
        float a[8] = {v0.x, v0.y, v0.z, v0.w, v1.x, v1.y, v1.z, v1.w};
        bf16 hi[8], lo[8];
#pragma unroll
        for (int k = 0; k < 8; k++) {
            hi[k] = __float2bfloat16(a[k]);
            lo[k] = __float2bfloat16(a[k] - __bfloat162float(hi[k]));
        }
        uint32_t off = r * 128 + ((sl8 ^ (r & 7)) * 16);
        *(uint4*)((char*)sh + off) = *(uint4*)hi;
        *(uint4*)((char*)sl + off) = *(uint4*)lo;
    }
}

// ---------------- far strided attention over residue classes ----------------
// CTA = (c, h): queries q = c + 64m, keys k = c + 64j, valid iff m - j >= 5
// (delta = 64(m-j) >= 320; smaller deltas belong to the window kernel).
// K/V of the whole residue class staged ONCE. Writes un-normalized partials.
__global__ __launch_bounds__(128) void far_attn_kernel()
{
    __shared__ __align__(128) bf16 sKH[4096];
    __shared__ __align__(128) bf16 sKL[4096];
    __shared__ __align__(128) bf16 sVH[4096];
    __shared__ __align__(128) bf16 sVL[4096];

    const int c  = blockIdx.x;
    const int h  = blockIdx.y;
    const int tid = threadIdx.x;
    const int lane = tid & 31;
    const int w = tid >> 5;
    const int row16 = lane >> 2;
    const int quad = lane & 3;
    const int mrow = w * 16 + row16;          // first owned m index
    const int q0row = c + 64 * mrow;          // global query row (m)
    const int q1row = q0row + 512;            // global query row (m+8)

    // Q scalars (pre-scaled), dims {8j + 2*quad + {0,1}}
    float q0[16], q1[16];
    {
        const float* qp0 = g_Q + (size_t)q0row * CDIM + h * HD;
        const float* qp1 = g_Q + (size_t)q1row * CDIM + h * HD;
#pragma unroll
        for (int j = 0; j < 8; j++) {
            float2 a = *(const float2*)(qp0 + 8 * j + 2 * quad);
            float2 b = *(const float2*)(qp1 + 8 * j + 2 * quad);
            q0[2 * j] = a.x * 0.125f; q0[2 * j + 1] = a.y * 0.125f;
            q1[2 * j] = b.x * 0.125f; q1[2 * j + 1] = b.y * 0.125f;
        }
    }
    uint32_t qh[4][4], ql[4][4];
#pragma unroll
    for (int kk = 0; kk < 4; kk++) {
        split_pack2(q0[4 * kk],     q0[4 * kk + 1], qh[kk][0], ql[kk][0]);
        split_pack2(q1[4 * kk],     q1[4 * kk + 1], qh[kk][1], ql[kk][1]);
        split_pack2(q0[4 * kk + 2], q0[4 * kk + 3], qh[kk][2], ql[kk][2]);
        split_pack2(q1[4 * kk + 2], q1[4 * kk + 3], qh[kk][3], ql[kk][3]);
    }

    stage_hl_s(g_K, c, 64, h, sKH, sKL, tid);
    stage_hl_s(g_V, c, 64, h, sVH, sVL, tid);
    __syncthreads();

    const uint32_t uKH = smem_u32(sKH), uKL = smem_u32(sKL);
    const uint32_t uVH = smem_u32(sVH), uVL = smem_u32(sVL);
    const int bmat = lane >> 3;
    const int brow_in = ((bmat & 2) ? 8 : 0) + (lane & 7);
    const int bslot_in = bmat & 1;
    const int v_row_in = ((lane >> 3) & 1) * 8 + (lane & 7);
    const int v_sel = lane >> 4;

    // ---- scores: 3-pass hi/lo ----
    float sacc[8][4];
#pragma unroll
    for (int t = 0; t < 8; t++)
#pragma unroll
        for (int cc = 0; cc < 4; cc++) sacc[t][cc] = 0.f;
#pragma unroll
    for (int kk = 0; kk < 4; kk++) {
#pragma unroll
        for (int np = 0; np < 4; np++) {
            int r = np * 16 + brow_in;
            uint32_t off = r * 128 + (((2 * kk + bslot_in) ^ (r & 7)) * 16);
            uint32_t b[4];
            LDSM_X4(b[0], b[1], b[2], b[3], uKH + off);
            MMA_BF16(sacc[2 * np],     qh[kk], b[0], b[1]);
            MMA_BF16(sacc[2 * np + 1], qh[kk], b[2], b[3]);
            MMA_BF16(sacc[2 * np],     ql[kk], b[0], b[1]);
            MMA_BF16(sacc[2 * np + 1], ql[kk], b[2], b[3]);
            LDSM_X4(b[0], b[1], b[2], b[3], uKL + off);
            MMA_BF16(sacc[2 * np],     qh[kk], b[0], b[1]);
            MMA_BF16(sacc[2 * np + 1], qh[kk], b[2], b[3]);
        }
    }

    // ---- mask (m - j >= 5) + softmax with empty-row guard ----
    float rmax0 = NEG_INF, rmax1 = NEG_INF;
#pragma unroll
    for (int t = 0; t < 8; t++) {
#pragma unroll
        for (int cc = 0; cc < 4; cc++) {
            int m = mrow + ((cc >> 1) ? 8 : 0);
            int j = t * 8 + 2 * quad + (cc & 1);
            float s = (m - j >= 5) ? sacc[t][cc] : NEG_INF;
            sacc[t][cc] = s;
            if (cc < 2) rmax0 = fmaxf(rmax0, s);
            else        rmax1 = fmaxf(rmax1, s);
        }
    }
    rmax0 = fmaxf(rmax0, __shfl_xor_sync(0xFFFFFFFFu, rmax0, 1));
    rmax0 = fmaxf(rmax0, __shfl_xor_sync(0xFFFFFFFFu, rmax0, 2));
    rmax1 = fmaxf(rmax1, __shfl_xor_sync(0xFFFFFFFFu, rmax1, 1));
    rmax1 = fmaxf(rmax1, __shfl_xor_sync(0xFFFFFFFFu, rmax1, 2));
    float base0 = (rmax0 > -1e29f) ? 1.f : 0.f;
    float base1 = (rmax1 > -1e29f) ? 1.f : 0.f;
    float sum0 = 0.f, sum1 = 0.f;
#pragma unroll
    for (int t = 0; t < 8; t++) {
#pragma unroll
        for (int cc = 0; cc < 4; cc++) {
            float bb = (cc < 2) ? base0 : base1;
            float mm = (cc < 2) ? rmax0 : rmax1;
            float p = bb * __expf(sacc[t][cc] - mm);
            sacc[t][cc] = p;
            if (cc < 2) sum0 += p; else sum1 += p;
        }
    }
    sum0 += __shfl_xor_sync(0xFFFFFFFFu, sum0, 1);
    sum0 += __shfl_xor_sync(0xFFFFFFFFu, sum0, 2);
    sum1 += __shfl_xor_sync(0xFFFFFFFFu, sum1, 1);
    sum1 += __shfl_xor_sync(0xFFFFFFFFu, sum1, 2);

    // ---- PV: 3-pass hi/lo ----
    float oacc[8][4];
#pragma unroll
    for (int t = 0; t < 8; t++)
#pragma unroll
        for (int cc = 0; cc < 4; cc++) oacc[t][cc] = 0.f;
#pragma unroll
    for (int j = 0; j < 4; j++) {
        uint32_t pfh[4], pfl[4];
        split_pack2(sacc[2 * j][0],     sacc[2 * j][1],     pfh[0], pfl[0]);
        split_pack2(sacc[2 * j][2],     sacc[2 * j][3],     pfh[1], pfl[1]);
        split_pack2(sacc[2 * j + 1][0], sacc[2 * j + 1][1], pfh[2], pfl[2]);
        split_pack2(sacc[2 * j + 1][2], sacc[2 * j + 1][3], pfh[3], pfl[3]);
#pragma unroll
        for (int np = 0; np < 4; np++) {
            int r = j * 16 + v_row_in;
            uint32_t off = r * 128 + (((2 * np + v_sel) ^ (r & 7)) * 16);
            uint32_t vh[4], vl[4];
            LDSM_X4_T(vh[0], vh[1], vh[2], vh[3], uVH + off);
            LDSM_X4_T(vl[0], vl[1], vl[2], vl[3], uVL + off);
            MMA_BF16(oacc[2 * np],     pfh, vh[0], vh[1]);
            MMA_BF16(oacc[2 * np],     pfl, vh[0], vh[1]);
            MMA_BF16(oacc[2 * np],     pfh, vl[0], vl[1]);
            MMA_BF16(oacc[2 * np + 1], pfh, vh[2], vh[3]);
            MMA_BF16(oacc[2 * np + 1], pfl, vh[2], vh[3]);
            MMA_BF16(oacc[2 * np + 1], pfh, vl[2], vl[3]);
        }
    }

    // ---- store un-normalized partials ----
#pragma unroll
    for (int t = 0; t < 8; t++) {
        int col = h * HD + t * 8 + 2 * quad;
        *(float2*)(g_FO + (size_t)q0row * CDIM + col) = make_float2(oacc[t][0], oacc[t][1]);
        *(float2*)(g_FO + (size_t)q1row * CDIM + col) = make_float2(oacc[t][2], oacc[t][3]);
    }
    if (quad == 0) {
        g_fm[q0row * NH + h] = rmax0;
        g_fl[q0row * NH + h] = sum0;
        g_fm[q1row * NH + h] = rmax1;
        g_fl[q1row * NH + h] = sum1;
    }
}

// ---------------- window attention + merge with far partials ----------------
__global__ __launch_bounds__(128) void attn_kernel()
{
    __shared__ __align__(128) bf16 sKH[4096];
    __shared__ __align__(128) bf16 sKL[4096];
    __shared__ __align__(128) bf16 sVH[4096];
    __shared__ __align__(128) bf16 sVL[4096];

    const int qb = blockIdx.x;
    const int h  = blockIdx.y;
    const int tid = threadIdx.x;
    const int lane = tid & 31;
    const int w = tid >> 5;
    const int row16 = lane >> 2;
    const int quad = lane & 3;
    const int r0g = qb * 64 + w * 16 + row16;

    float q0[16], q1[16];
    {
        const float* qp0 = g_Q + (size_t)r0g * CDIM + h * HD;
#pragma unroll
        for (int j = 0; j < 8; j++) {
            float2 a = *(const float2*)(qp0 + 8 * j + 2 * quad);
            float2 b = *(const float2*)(qp0 + 8 * CDIM + 8 * j + 2 * quad);
            q0[2 * j] = a.x * 0.125f; q0[2 * j + 1] = a.y * 0.125f;
            q1[2 * j] = b.x * 0.125f; q1[2 * j + 1] = b.y * 0.125f;
        }
    }
    uint32_t qh[4][4], ql[4][4];
#pragma unroll
    for (int kk = 0; kk < 4; kk++) {
        split_pack2(q0[4 * kk],     q0[4 * kk + 1], qh[kk][0], ql[kk][0]);
        split_pack2(q1[4 * kk],     q1[4 * kk + 1], qh[kk][1], ql[kk][1]);
        split_pack2(q0[4 * kk + 2], q0[4 * kk + 3], qh[kk][2], ql[kk][2]);
        split_pack2(q1[4 * kk + 2], q1[4 * kk + 3], qh[kk][3], ql[kk][3]);
    }

    float oacc[8][4];
#pragma unroll
    for (int t = 0; t < 8; t++)
#pragma unroll
        for (int cc = 0; cc < 4; cc++) oacc[t][cc] = 0.f;
    float m0 = NEG_INF, m1 = NEG_INF, l0 = 0.f, l1 = 0.f;

    const uint32_t uKH = smem_u32(sKH), uKL = smem_u32(sKL);
    const uint32_t uVH = smem_u32(sVH), uVL = smem_u32(sVL);
    const int bmat = lane >> 3;
    const int brow_in = ((bmat & 2) ? 8 : 0) + (lane & 7);
    const int bslot_in = bmat & 1;
    const int v_row_in = ((lane >> 3) & 1) * 8 + (lane & 7);
    const int v_sel = lane >> 4;
    const int wstart = (qb >= 4) ? qb - 4 : 0;

#pragma unroll 1
    for (int kb = wstart; kb <= qb; ++kb) {
        __syncthreads();
        stage_hl_s(g_K, kb * 64, 1, h, sKH, sKL, tid);
        stage_hl_s(g_V, kb * 64, 1, h, sVH, sVL, tid);
        __syncthreads();

        float sacc[8][4];
#pragma unroll
        for (int t = 0; t < 8; t++)
#pragma unroll
            for (int cc = 0; cc < 4; cc++) sacc[t][cc] = 0.f;
#pragma unroll
        for (int kk = 0; kk < 4; kk++) {
#pragma unroll
            for (int np = 0; np < 4; np++) {
                int r = np * 16 + brow_in;
                uint32_t off = r * 128 + (((2 * kk + bslot_in) ^ (r & 7)) * 16);
                uint32_t b[4];
                LDSM_X4(b[0], b[1], b[2], b[3], uKH + off);
                MMA_BF16(sacc[2 * np],     qh[kk], b[0], b[1]);
                MMA_BF16(sacc[2 * np + 1], qh[kk], b[2], b[3]);
                MMA_BF16(sacc[2 * np],     ql[kk], b[0], b[1]);
                MMA_BF16(sacc[2 * np + 1], ql[kk], b[2], b[3]);
                LDSM_X4(b[0], b[1], b[2], b[3], uKL + off);
                MMA_BF16(sacc[2 * np],     qh[kk], b[0], b[1]);
                MMA_BF16(sacc[2 * np + 1], qh[kk], b[2], b[3]);
            }
        }
        float rmax0 = NEG_INF, rmax1 = NEG_INF;
#pragma unroll
        for (int t = 0; t < 8; t++) {
#pragma unroll
            for (int cc = 0; cc < 4; cc++) {
                int row = r0g + ((cc >> 1) ? 8 : 0);
                int col = kb * 64 + t * 8 + 2 * quad + (cc & 1);
                int delta = row - col;
                bool valid = (delta >= 0) && ((delta <= 255) || ((delta & 63) == 0));
                float s = valid ? sacc[t][cc] : NEG_INF;
                sacc[t][cc] = s;
                if (cc < 2) rmax0 = fmaxf(rmax0, s);
                else        rmax1 = fmaxf(rmax1, s);
            }
        }
        rmax0 = fmaxf(rmax0, __shfl_xor_sync(0xFFFFFFFFu, rmax0, 1));
        rmax0 = fmaxf(rmax0, __shfl_xor_sync(0xFFFFFFFFu, rmax0, 2));
        rmax1 = fmaxf(rmax1, __shfl_xor_sync(0xFFFFFFFFu, rmax1, 1));
        rmax1 = fmaxf(rmax1, __shfl_xor_sync(0xFFFFFFFFu, rmax1, 2));
        float mn0 = fmaxf(m0, rmax0), mn1 = fmaxf(m1, rmax1);
        float c0 = __expf(m0 - mn0), c1 = __expf(m1 - mn1);
        float sum0 = 0.f, sum1 = 0.f;
#pragma unroll
        for (int t = 0; t < 8; t++) {
#pragma unroll
            for (int cc = 0; cc < 4; cc++) {
                float p = __expf(sacc[t][cc] - ((cc < 2) ? mn0 : mn1));
                sacc[t][cc] = p;
                if (cc < 2) sum0 += p; else sum1 += p;
            }
        }
        sum0 += __shfl_xor_sync(0xFFFFFFFFu, sum0, 1);
        sum0 += __shfl_xor_sync(0xFFFFFFFFu, sum0, 2);
        sum1 += __shfl_xor_sync(0xFFFFFFFFu, sum1, 1);
        sum1 += __shfl_xor_sync(0xFFFFFFFFu, sum1, 2);
        l0 = l0 * c0 + sum0;
        l1 = l1 * c1 + sum1;
#pragma unroll
        for (int t = 0; t < 8; t++) {
            oacc[t][0] *= c0; oacc[t][1] *= c0;
            oacc[t][2] *= c1; oacc[t][3] *= c1;
        }
        m0 = mn0; m1 = mn1;

#pragma unroll
        for (int j = 0; j < 4; j++) {
            uint32_t pfh[4], pfl[4];
            split_pack2(sacc[2 * j][0],     sacc[2 * j][1],     pfh[0], pfl[0]);
            split_pack2(sacc[2 * j][2],     sacc[2 * j][3],     pfh[1], pfl[1]);
            split_pack2(sacc[2 * j + 1][0], sacc[2 * j + 1][1], pfh[2], pfl[2]);
            split_pack2(sacc[2 * j + 1][2], sacc[2 * j + 1][3], pfh[3], pfl[3]);
#pragma unroll
            for (int np = 0; np < 4; np++) {
                int r = j * 16 + v_row_in;
                uint32_t off = r * 128 + (((2 * np + v_sel) ^ (r & 7)) * 16);
                uint32_t vh[4], vl[4];
                LDSM_X4_T(vh[0], vh[1], vh[2], vh[3], uVH + off);
                LDSM_X4_T(vl[0], vl[1], vl[2], vl[3], uVL + off);
                MMA_BF16(oacc[2 * np],     pfh, vh[0], vh[1]);
                MMA_BF16(oacc[2 * np],     pfl, vh[0], vh[1]);
                MMA_BF16(oacc[2 * np],     pfh, vl[0], vl[1]);
                MMA_BF16(oacc[2 * np + 1], pfh, vh[2], vh[3]);
                MMA_BF16(oacc[2 * np + 1], pfl, vh[2], vh[3]);
                MMA_BF16(oacc[2 * np + 1], pfh, vl[2], vl[3]);
            }
        }
    }

    // ---- merge with far partials, normalize, store ----
    float fm0 = g_fm[r0g * NH + h];
    float fl0 = g_fl[r0g * NH + h];
    float fm1 = g_fm[(r0g + 8) * NH + h];
    float fl1 = g_fl[(r0g + 8) * NH + h];
    float mn0 = fmaxf(m0, fm0), mn1 = fmaxf(m1, fm1);
    float a0 = __expf(m0 - mn0), b0 = __expf(fm0 - mn0);
    float a1 = __expf(m1 - mn1), b1 = __expf(fm1 - mn1);
    float inv0 = 1.f / (a0 * l0 + b0 * fl0);
    float inv1 = 1.f / (a1 * l1 + b1 * fl1);
#pragma unroll
    for (int t = 0; t < 8; t++) {
        int col = h * HD + t * 8 + 2 * quad;
        float2 f0 = *(const float2*)(g_FO + (size_t)r0g * CDIM + col);
        float2 f1 = *(const float2*)(g_FO + (size_t)(r0g + 8) * CDIM + col);
        float* p0 = g_O + (size_t)r0g * CDIM + col;
        float* p1 = g_O + (size_t)(r0g + 8) * CDIM + col;
        *(float2*)p0 = make_float2((a0 * oacc[t][0] + b0 * f0.x) * inv0,
                                   (a0 * oacc[t][1] + b0 * f0.y) * inv0);
        *(float2*)p1 = make_float2((a1 * oacc[t][2] + b1 * f1.x) * inv1,
                                   (a1 * oacc[t][3] + b1 * f1.y) * inv1);
    }
}

// ---------------- launch ----------------
extern "C" void kernel_launch(void* const* d_in, const int* in_sizes, int n_in,
                              void* d_out, int out_size)
{
    const float* x  = (const float*)d_in[0];
    const float* Wq = (const float*)d_in[1];
    const float* Wk = (const float*)d_in[2];
    const float* Wv = (const float*)d_in[3];
    const float* Wo = (const float*)d_in[4];
    float* out = (float*)d_out;

    cudaFuncSetAttribute(qkv_gemm,   cudaFuncAttributeMaxDynamicSharedMemorySize, SMEM_GEMM);
    cudaFuncSetAttribute(oproj_gemm, cudaFuncAttributeMaxDynamicSharedMemorySize, SMEM_GEMM);

    bf16 *xh, *xl, *wh, *wl, *oh, *ol;
    cudaGetSymbolAddress((void**)&xh, g_xh);
    cudaGetSymbolAddress((void**)&xl, g_xl);
    cudaGetSymbolAddress((void**)&wh, g_wh);
    cudaGetSymbolAddress((void**)&wl, g_wl);
    cudaGetSymbolAddress((void**)&oh, g_oh);
    cudaGetSymbolAddress((void**)&ol, g_ol);
    float* oPtr;
    cudaGetSymbolAddress((void**)&oPtr, g_O);

    convert_split<<<(Tseq * CDIM / 4 + 255) / 256, 256>>>(x, xh, xl, Tseq * CDIM / 4);
    convert_split<<<(WSZ / 4 + 255) / 256, 256>>>(Wq, wh + 0 * (size_t)WSZ, wl + 0 * (size_t)WSZ, WSZ / 4);
    convert_split<<<(WSZ / 4 + 255) / 256, 256>>>(Wk, wh + 1 * (size_t)WSZ, wl + 1 * (size_t)WSZ, WSZ / 4);
    convert_split<<<(WSZ / 4 + 255) / 256, 256>>>(Wv, wh + 2 * (size_t)WSZ, wl + 2 * (size_t)WSZ, WSZ / 4);
    convert_split<<<(WSZ / 4 + 255) / 256, 256>>>(Wo, wh + 3 * (size_t)WSZ, wl + 3 * (size_t)WSZ, WSZ / 4);

    qkv_gemm<<<dim3(CDIM / 128, Tseq / 128, 3), 256, SMEM_GEMM>>>();

    far_attn_kernel<<<dim3(64, NH), 128>>>();
    attn_kernel<<<dim3(Tseq / 64, NH), 128>>>();

    convert_split<<<(Tseq * CDIM / 4 + 255) / 256, 256>>>(oPtr, oh, ol, Tseq * CDIM / 4);

    oproj_gemm<<<dim3(CDIM / 128, Tseq / 128), 256, SMEM_GEMM>>>(out);
}